// round 7
// baseline (speedup 1.0000x reference)
#include <cuda_runtime.h>
#include <cuda_bf16.h>
#include <cstdint>

#define BBATCH 4
#define SSZ 384
#define DD 300
#define EE 50
#define HH 150
#define BSR (BBATCH*SSZ)   /* 1536 */
#define D1 450
#define INVE (1.0f/50.0f)

// ---------------- device scratch ----------------
__device__ float g_we[EE];
__device__ float g_w1s[HH];
__device__ float g_w2s[HH];
__device__ float g_sbh;
__device__ float g_A0[BBATCH*SSZ*SSZ];
__device__ float g_A1[BBATCH*SSZ*SSZ];
__device__ float g_Q [BSR*HH];
__device__ float g_P [BSR*HH];
__device__ float g_OX[BSR*DD];
__device__ float g_s1[BSR];
__device__ float g_s2[BSR];
__device__ float g_c0a[BSR*HH];   // bat0 split-K partials
__device__ float g_c0b[BSR*HH];
__device__ float g_c1a[BSR*HH];   // bat1 split-K partials
__device__ float g_c1b[BSR*HH];

// ---------------- prep ------------------------------------------------------
__global__ void prep_weights(const float* __restrict__ Wh, const float* __restrict__ bh) {
    int t = threadIdx.x;
    const int WHC = 2*HH + EE;
    if (t < EE) {
        float s = 0.f;
        for (int f = 0; f < EE; f++) s += Wh[f*WHC + t];
        g_we[t] = s;
    }
    if (t < HH) {
        float a = 0.f, b = 0.f;
        for (int f = 0; f < EE; f++) {
            a += Wh[f*WHC + EE + t];
            b += Wh[f*WHC + EE + HH + t];
        }
        g_w1s[t] = a;
        g_w2s[t] = b;
    }
    if (t == 0) {
        float s = 0.f;
        for (int e = 0; e < EE; e++) s += bh[e];
        g_sbh = s;
    }
}

// ---- bf16 hi/lo split of a float pair, packed as bf16x2 --------------------
__device__ __forceinline__ void split2(float x, float y, uint32_t& hi, uint32_t& lo) {
    __nv_bfloat16 hx = __float2bfloat16(x);
    __nv_bfloat16 hy = __float2bfloat16(y);
    __nv_bfloat16 lx = __float2bfloat16(x - __bfloat162float(hx));
    __nv_bfloat16 ly = __float2bfloat16(y - __bfloat162float(hy));
    __nv_bfloat162 h2(hx, hy), l2(lx, ly);
    hi = *reinterpret_cast<uint32_t*>(&h2);
    lo = *reinterpret_cast<uint32_t*>(&l2);
}

__device__ __forceinline__ void mma_bf16(float* c, const uint32_t* a, uint32_t b0, uint32_t b1) {
    asm volatile(
        "mma.sync.aligned.m16n8k16.row.col.f32.bf16.bf16.f32 "
        "{%0,%1,%2,%3}, {%4,%5,%6,%7}, {%8,%9}, {%0,%1,%2,%3};"
        : "+f"(c[0]), "+f"(c[1]), "+f"(c[2]), "+f"(c[3])
        : "r"(a[0]), "r"(a[1]), "r"(a[2]), "r"(a[3]), "r"(b0), "r"(b1));
}

// ---- A-operand loader for SIMT NT GEMMs ------------------------------------
template<int ASRC>
__device__ __forceinline__ void ldA8(float* ar, const float* __restrict__ A, int lda,
                                     const float* __restrict__ ba,
                                     int m, int kq, int K) {
    if (ASRC == 0) {
        const float* p = A + (size_t)m * lda;
        #pragma unroll
        for (int h = 0; h < 2; h++) {
            int k = kq + h*8;
            float4 v = (k < K) ? *(const float4*)(p + k) : make_float4(0.f,0.f,0.f,0.f);
            ar[h*4+0]=v.x; ar[h*4+1]=v.y; ar[h*4+2]=v.z; ar[h*4+3]=v.w;
        }
    } else {
        const float* pa = (ASRC==1) ? g_c0a : g_c1a;
        const float* pb = (ASRC==1) ? g_c0b : g_c1b;
        const float* pq = (ASRC==1) ? g_Q   : g_P;
        size_t base = (size_t)m * HH;
        #pragma unroll
        for (int h = 0; h < 2; h++) {
            #pragma unroll
            for (int t = 0; t < 2; t++) {
                int k = kq + h*8 + t*2;
                float rx = 0.f, ry = 0.f;
                if (k < K) {
                    float2 a = *(const float2*)(pa + base + k);
                    float2 b = *(const float2*)(pb + base + k);
                    float2 q = *(const float2*)(pq + base + k);
                    float2 bb = *(const float2*)(ba + k);
                    rx = fmaxf(fmaf(a.x + b.x, INVE, q.x + 2.f*bb.x), 0.f);
                    ry = fmaxf(fmaf(a.y + b.y, INVE, q.y + 2.f*bb.y), 0.f);
                }
                ar[h*4 + t*2] = rx; ar[h*4 + t*2 + 1] = ry;
            }
        }
    }
}

// ======= NT GEMM core: 64x32 tile, 128 thr, 4x4 micro, C = A@W^T ============
template<int ASRC>
__device__ __forceinline__ void ntB(
    const float* __restrict__ A, int lda, int K,
    const float* __restrict__ baA,
    const float* __restrict__ W, int ldw, int N,
    int m0, int n0,
    const float* __restrict__ biasC, const float* __restrict__ Cadd,
    float* __restrict__ C, int ldc)
{
    __shared__ __align__(16) float As[16][68];
    __shared__ __align__(16) float Ws[16][36];
    int tid = threadIdx.x;
    int arow = tid >> 1, aq = (tid & 1) * 4;
    int wrow = tid >> 2, wq = (tid & 3) * 2;
    int tx = tid & 7, ty = tid >> 3;
    int NIT = (K + 15) >> 4;

    int mA = m0 + arow;
    int nW = n0 + wrow;
    bool nok = nW < N;
    const float* Wrow = W + (size_t)(nok ? nW : 0) * ldw;

    float ar[8], wr[4];
    float acc[4][4] = {};

    ldA8<ASRC>(ar, A, lda, baA, mA, aq, K);
    #pragma unroll
    for (int h = 0; h < 2; h++) {
        int k = wq + h*8;
        float2 v = (nok && k < K) ? *(const float2*)(Wrow + k) : make_float2(0.f,0.f);
        wr[h*2] = v.x; wr[h*2+1] = v.y;
    }

    for (int it = 0; it < NIT; it++) {
        __syncthreads();
        #pragma unroll
        for (int h = 0; h < 2; h++)
            #pragma unroll
            for (int j = 0; j < 4; j++)
                As[aq + h*8 + j][arow] = ar[h*4 + j];
        #pragma unroll
        for (int h = 0; h < 2; h++)
            #pragma unroll
            for (int j = 0; j < 2; j++)
                Ws[wq + h*8 + j][wrow] = wr[h*2 + j];
        __syncthreads();
        if (it + 1 < NIT) {
            int k0 = (it + 1) * 16;
            ldA8<ASRC>(ar, A, lda, baA, mA, k0 + aq, K);
            #pragma unroll
            for (int h = 0; h < 2; h++) {
                int k = k0 + wq + h*8;
                float2 v = (nok && k < K) ? *(const float2*)(Wrow + k) : make_float2(0.f,0.f);
                wr[h*2] = v.x; wr[h*2+1] = v.y;
            }
        }
        #pragma unroll
        for (int kk = 0; kk < 16; kk++) {
            float4 a = *(const float4*)&As[kk][ty*4];
            float4 w = *(const float4*)&Ws[kk][tx*4];
            float am[4] = {a.x,a.y,a.z,a.w};
            float wn[4] = {w.x,w.y,w.z,w.w};
            #pragma unroll
            for (int i = 0; i < 4; i++)
                #pragma unroll
                for (int j = 0; j < 4; j++)
                    acc[i][j] = fmaf(am[i], wn[j], acc[i][j]);
        }
    }

    #pragma unroll
    for (int i = 0; i < 4; i++) {
        int m = m0 + ty*4 + i;
        #pragma unroll
        for (int j = 0; j < 4; j++) {
            int n = n0 + tx*4 + j;
            if (n < N) {
                float v = acc[i][j];
                if (biasC) v += biasC[n];
                if (Cadd) v += Cadd[(size_t)m*ldc + n];
                C[(size_t)m*ldc + n] = v;
            }
        }
    }
}

// ======= stage1: Q, PX, OX GEMMs + adj reduction ============================
#define QB 120
#define PXB 120
#define OXB 240
#define GEMMB (QB+PXB+OXB)      /* 480 */
#define ADJ_RPB 64
#define ADJ_BLOCKS (BBATCH*SSZ*SSZ/ADJ_RPB)   /* 9216 */

__global__ __launch_bounds__(128) void stage1(
    const float* __restrict__ adj, const float* __restrict__ X,
    const float* __restrict__ W0, const float* __restrict__ W1,
    const float* __restrict__ Wout, const float* __restrict__ bout)
{
    int bx = blockIdx.x;
    if (bx < QB) {               // Q = X @ W0^T
        ntB<0>(X, DD, DD, nullptr, W0, DD, HH, (bx/5)*64, (bx%5)*32,
               nullptr, nullptr, g_Q, HH);
        return;
    }
    if (bx < QB + PXB) {         // PX = X @ W1[:, :300]^T
        int t = bx - QB;
        ntB<0>(X, DD, DD, nullptr, W1, D1, HH, (t/5)*64, (t%5)*32,
               nullptr, nullptr, g_P, HH);
        return;
    }
    if (bx < GEMMB) {            // OX = X @ Wout^T + bout
        int t = bx - QB - PXB;
        ntB<0>(X, DD, DD, nullptr, Wout, DD, DD, (t/10)*64, (t%10)*32,
               bout, nullptr, g_OX, DD);
        return;
    }
    // ---- adj reduction: 64 rows/block, smem-staged ----
    __shared__ float buf[ADJ_RPB][51];
    __shared__ float swe[EE];
    int tid = threadIdx.x;
    if (tid < EE) swe[tid] = g_we[tid];
    size_t r0 = (size_t)(bx - GEMMB) * ADJ_RPB;
    const float4* src = (const float4*)(adj + r0 * EE);
    for (int idx = tid; idx < ADJ_RPB*EE/4; idx += 128) {
        float4 v = src[idx];
        int g = idx * 4;
        buf[(g  )/EE][(g  )%EE] = v.x;
        buf[(g+1)/EE][(g+1)%EE] = v.y;
        buf[(g+2)/EE][(g+2)%EE] = v.z;
        buf[(g+3)/EE][(g+3)%EE] = v.w;
    }
    __syncthreads();
    if (tid < ADJ_RPB) {
        float s0 = 0.f, s1 = 0.f;
        #pragma unroll 10
        for (int e = 0; e < EE; e++) {
            float v = buf[tid][e];
            s0 += v;
            s1 = fmaf(v, swe[e], s1);
        }
        g_A0[r0 + tid] = s0;
        g_A1[r0 + tid] = s1;
    }
}

// ======= bat_mma: batched GEMM via mma.sync bf16 hi/lo split ================
// grid (nx=2, my=6, z=8: b*2+half). Tile M=64 (16/warp), N=80, K=192/half.
// C_partial = A(@fold) @ B via Ahi@Bhi + Ahi@Blo + Alo@Bhi.
template<int MODE>
__global__ __launch_bounds__(128) void bat_mma() {
    __shared__ uint32_t Ah[64][17], Al[64][17];   // bf16x2 k-pairs, 16 per k32 chunk
    __shared__ uint32_t Bh[80][17], Bl[80][17];   // [n][k-pair]
    int tid = threadIdx.x, wid = tid >> 5, lane = tid & 31;
    int gid = lane >> 2, tig = lane & 3;
    int b = blockIdx.z >> 1, half = blockIdx.z & 1;
    const float* Ab = (MODE==0 ? g_A0 : g_A1) + (size_t)b * SSZ * SSZ;
    const float* Bb = (MODE==0 ? g_Q  : g_P ) + (size_t)b * SSZ * HH;
    float* Cp = (MODE==0) ? (half ? g_c0b : g_c0a) : (half ? g_c1b : g_c1a);
    int m0 = blockIdx.y * 64, n0 = blockIdx.x * 80;
    int kbase = half * 192;
    const float sbh = g_sbh;

    float acc[10][4] = {};

    for (int kc = 0; kc < 6; kc++) {
        int k0 = kbase + kc * 32;
        // ---- A tile 64x32: fp32 (+fold) -> hi/lo bf16x2 pairs ----
        {
            int row = tid >> 1;
            int cq = (tid & 1) * 8;      // base pair index (8 pairs = 16 floats)
            const float* src = Ab + (size_t)(m0 + row) * SSZ + k0 + cq*2;
            float s2m = 0.f;
            if (MODE == 1) s2m = g_s2[b*SSZ + m0 + row] + sbh;
            #pragma unroll
            for (int q = 0; q < 4; q++) {
                float4 v = *(const float4*)(src + q*4);
                if (MODE == 1) {
                    float4 s = *(const float4*)(g_s1 + b*SSZ + k0 + cq*2 + q*4);
                    v.x += s.x + s2m; v.y += s.y + s2m;
                    v.z += s.z + s2m; v.w += s.w + s2m;
                }
                uint32_t h0, l0, h1, l1;
                split2(v.x, v.y, h0, l0);
                split2(v.z, v.w, h1, l1);
                Ah[row][cq + q*2]     = h0;  Al[row][cq + q*2]     = l0;
                Ah[row][cq + q*2 + 1] = h1;  Al[row][cq + q*2 + 1] = l1;
            }
        }
        // ---- B tile 32(k)x80(n), transposed to [n][k-pair] ----
        for (int idx = tid; idx < 16*80; idx += 128) {
            int k2 = idx / 80, n = idx % 80;
            int gn = n0 + n;
            float x = 0.f, y = 0.f;
            if (gn < HH) {
                x = Bb[(size_t)(k0 + 2*k2)     * HH + gn];
                y = Bb[(size_t)(k0 + 2*k2 + 1) * HH + gn];
            }
            uint32_t h, l;
            split2(x, y, h, l);
            Bh[n][k2] = h;
            Bl[n][k2] = l;
        }
        __syncthreads();
        // ---- 2 x k16 mma steps ----
        int arow = wid * 16 + gid;
        #pragma unroll
        for (int s = 0; s < 2; s++) {
            int kp = s * 8;
            uint32_t ah[4], al[4];
            ah[0] = Ah[arow    ][kp + tig];     al[0] = Al[arow    ][kp + tig];
            ah[1] = Ah[arow + 8][kp + tig];     al[1] = Al[arow + 8][kp + tig];
            ah[2] = Ah[arow    ][kp + tig + 4]; al[2] = Al[arow    ][kp + tig + 4];
            ah[3] = Ah[arow + 8][kp + tig + 4]; al[3] = Al[arow + 8][kp + tig + 4];
            #pragma unroll
            for (int nf = 0; nf < 10; nf++) {
                int nr = nf * 8 + gid;
                uint32_t bh0 = Bh[nr][kp + tig], bh1 = Bh[nr][kp + tig + 4];
                uint32_t bl0 = Bl[nr][kp + tig], bl1 = Bl[nr][kp + tig + 4];
                mma_bf16(acc[nf], ah, bh0, bh1);
                mma_bf16(acc[nf], ah, bl0, bl1);
                mma_bf16(acc[nf], al, bh0, bh1);
            }
        }
        __syncthreads();
    }

    // ---- epilogue: c0,c1 -> (row gid, n 2tig,2tig+1); c2,c3 -> row gid+8 ----
    int mrow = m0 + wid * 16 + gid;
    size_t base0 = ((size_t)b * SSZ + mrow) * HH;
    size_t base1 = ((size_t)b * SSZ + mrow + 8) * HH;
    #pragma unroll
    for (int nf = 0; nf < 10; nf++) {
        int n = n0 + nf * 8 + 2 * tig;
        if (n < HH) {
            *(float2*)&Cp[base0 + n] = make_float2(acc[nf][0], acc[nf][1]);
            *(float2*)&Cp[base1 + n] = make_float2(acc[nf][2], acc[nf][3]);
        }
    }
}

// ======= stage3: P += g0@W1b^T ; OX += g0@WoutA^T ; s1/s2 ===================
#define PAB 120
#define OAB 240
__global__ __launch_bounds__(128) void stage3(const float* __restrict__ W1,
                                              const float* __restrict__ Wout,
                                              const float* __restrict__ b0) {
    int bx = blockIdx.x;
    if (bx < PAB) {
        ntB<1>(nullptr, 0, HH, b0, W1 + DD, D1, HH, (bx/5)*64, (bx%5)*32,
               nullptr, g_P, g_P, HH);
        return;
    }
    if (bx < PAB + OAB) {
        int t = bx - PAB;
        ntB<1>(nullptr, 0, HH, b0, Wout, DD, DD, (t/10)*64, (t%10)*32,
               nullptr, g_OX, g_OX, DD);
        return;
    }
    // s1/s2: thread per row of g0 (recompute epilogue on load)
    __shared__ float sw1[HH], sw2[HH], sb0[HH];
    int tid = threadIdx.x;
    for (int i = tid; i < HH; i += 128) {
        sw1[i] = g_w1s[i]; sw2[i] = g_w2s[i]; sb0[i] = b0[i];
    }
    __syncthreads();
    int row = (bx - PAB - OAB) * 128 + tid;
    const float* pa = g_c0a + (size_t)row * HH;
    const float* pb = g_c0b + (size_t)row * HH;
    const float* pq = g_Q   + (size_t)row * HH;
    float a1 = 0.f, a2 = 0.f;
    for (int k = 0; k < HH; k += 2) {
        float2 a = *(const float2*)(pa + k);
        float2 b = *(const float2*)(pb + k);
        float2 q = *(const float2*)(pq + k);
        float gx = fmaxf(fmaf(a.x + b.x, INVE, q.x + 2.f*sb0[k]),   0.f);
        float gy = fmaxf(fmaf(a.y + b.y, INVE, q.y + 2.f*sb0[k+1]), 0.f);
        a1 = fmaf(gx, sw1[k], a1);  a1 = fmaf(gy, sw1[k+1], a1);
        a2 = fmaf(gx, sw2[k], a2);  a2 = fmaf(gy, sw2[k+1], a2);
    }
    g_s1[row] = a1;
    g_s2[row] = a2;
}

// ======= stage6: out = OX + g1@WoutB^T ======================================
__global__ __launch_bounds__(128) void stage6(const float* __restrict__ Wout,
                                              const float* __restrict__ b1,
                                              float* __restrict__ out) {
    int bx = blockIdx.x;
    ntB<2>(nullptr, 0, HH, b1, Wout + HH, DD, DD, (bx/10)*64, (bx%10)*32,
           nullptr, g_OX, out, DD);
}

// ======= launch =============================================================
extern "C" void kernel_launch(void* const* d_in, const int* in_sizes, int n_in,
                              void* d_out, int out_size) {
    const float* adj  = (const float*)d_in[0];
    const float* X    = (const float*)d_in[1];
    const float* W0   = (const float*)d_in[2];
    const float* b0   = (const float*)d_in[3];
    const float* W1   = (const float*)d_in[4];
    const float* b1   = (const float*)d_in[5];
    const float* Wh   = (const float*)d_in[6];
    const float* bh   = (const float*)d_in[7];
    const float* Wout = (const float*)d_in[8];
    const float* bout = (const float*)d_in[9];
    float* out = (float*)d_out;

    prep_weights<<<1, 256>>>(Wh, bh);

    // Q, PX, OX GEMMs overlapped with the 118MB adj streaming pass
    stage1<<<GEMMB + ADJ_BLOCKS, 128>>>(adj, X, W0, W1, Wout, bout);

    // split-K partials of A0@Q via mma.sync (bf16 hi/lo split)
    bat_mma<0><<<dim3(2, 6, 8), 128>>>();

    // P += g0@W1b^T ; OX += g0@WoutA^T ; s1/s2   (g0 epilogue fused in loads)
    stage3<<<PAB + OAB + 12, 128>>>(W1, Wout, b0);

    // split-K partials of Atilde1@P via mma.sync (fold applied in fp32 pre-split)
    bat_mma<1><<<dim3(2, 6, 8), 128>>>();

    // out = OX + g1@WoutB^T   (g1 epilogue fused in loads)
    stage6<<<OAB, 128>>>(Wout, b1, out);
}

// round 9
// speedup vs baseline: 1.0875x; 1.0875x over previous
#include <cuda_runtime.h>
#include <cstdint>

#define BBATCH 4
#define SSZ 384
#define DD 300
#define EE 50
#define HH 150
#define BSR (BBATCH*SSZ)   /* 1536 */
#define D1 450
#define INVE (1.0f/50.0f)

// ---------------- device scratch ----------------
__device__ float g_we[EE];
__device__ float g_w1s[HH];
__device__ float g_w2s[HH];
__device__ float g_sbh;
__device__ float g_A0[BBATCH*SSZ*SSZ];
__device__ float g_A1[BBATCH*SSZ*SSZ];
__device__ float g_Q [BSR*HH];
__device__ float g_P [BSR*HH];
__device__ float g_OX[BSR*DD];
__device__ float g_s1[BSR];
__device__ float g_s2[BSR];
__device__ float g_c0a[BSR*HH];   // bat0 split-K partials
__device__ float g_c0b[BSR*HH];
__device__ float g_c1a[BSR*HH];   // bat1 split-K partials
__device__ float g_c1b[BSR*HH];

// ---------------- prep ------------------------------------------------------
__global__ void prep_weights(const float* __restrict__ Wh, const float* __restrict__ bh) {
    int t = threadIdx.x;
    const int WHC = 2*HH + EE;
    if (t < EE) {
        float s = 0.f;
        for (int f = 0; f < EE; f++) s += Wh[f*WHC + t];
        g_we[t] = s;
    }
    if (t < HH) {
        float a = 0.f, b = 0.f;
        for (int f = 0; f < EE; f++) {
            a += Wh[f*WHC + EE + t];
            b += Wh[f*WHC + EE + HH + t];
        }
        g_w1s[t] = a;
        g_w2s[t] = b;
    }
    if (t == 0) {
        float s = 0.f;
        for (int e = 0; e < EE; e++) s += bh[e];
        g_sbh = s;
    }
}

// ---- A-operand loaders (round-5 proven) -------------------------------------
// ASRC 0: raw fp32 matrix A (lda)
// ASRC 1: g0 = relu((c0a+c0b)/E + Q + 2*b0)
// ASRC 2: g1 = relu((c1a+c1b)/E + P + 2*b1)
template<int ASRC>
__device__ __forceinline__ void ldA8(float* ar, const float* __restrict__ A, int lda,
                                     const float* __restrict__ ba,
                                     int m, int kq, int K) {
    if (ASRC == 0) {
        const float* p = A + (size_t)m * lda;
        #pragma unroll
        for (int h = 0; h < 2; h++) {
            int k = kq + h*8;
            float4 v = (k < K) ? *(const float4*)(p + k) : make_float4(0.f,0.f,0.f,0.f);
            ar[h*4+0]=v.x; ar[h*4+1]=v.y; ar[h*4+2]=v.z; ar[h*4+3]=v.w;
        }
    } else {
        const float* pa = (ASRC==1) ? g_c0a : g_c1a;
        const float* pb = (ASRC==1) ? g_c0b : g_c1b;
        const float* pq = (ASRC==1) ? g_Q   : g_P;
        size_t base = (size_t)m * HH;
        #pragma unroll
        for (int h = 0; h < 2; h++) {
            #pragma unroll
            for (int t = 0; t < 2; t++) {
                int k = kq + h*8 + t*2;
                float rx = 0.f, ry = 0.f;
                if (k < K) {
                    float2 a = *(const float2*)(pa + base + k);
                    float2 b = *(const float2*)(pb + base + k);
                    float2 q = *(const float2*)(pq + base + k);
                    float2 bb = *(const float2*)(ba + k);
                    rx = fmaxf(fmaf(a.x + b.x, INVE, q.x + 2.f*bb.x), 0.f);
                    ry = fmaxf(fmaf(a.y + b.y, INVE, q.y + 2.f*bb.y), 0.f);
                }
                ar[h*4 + t*2] = rx; ar[h*4 + t*2 + 1] = ry;
            }
        }
    }
}

// ======= NT GEMM core: 64x32 tile, 128 thr, 4x4 micro, C = A@W^T ============
template<int ASRC>
__device__ __forceinline__ void ntB(
    const float* __restrict__ A, int lda, int K,
    const float* __restrict__ baA,
    const float* __restrict__ W, int ldw, int N,
    int m0, int n0,
    const float* __restrict__ biasC, const float* __restrict__ Cadd,
    float* __restrict__ C, int ldc)
{
    __shared__ __align__(16) float As[16][68];
    __shared__ __align__(16) float Ws[16][36];
    int tid = threadIdx.x;
    int arow = tid >> 1, aq = (tid & 1) * 4;
    int wrow = tid >> 2, wq = (tid & 3) * 2;
    int tx = tid & 7, ty = tid >> 3;
    int NIT = (K + 15) >> 4;

    int mA = m0 + arow;
    int nW = n0 + wrow;
    bool nok = nW < N;
    const float* Wrow = W + (size_t)(nok ? nW : 0) * ldw;

    float ar[8], wr[4];
    float acc[4][4] = {};

    ldA8<ASRC>(ar, A, lda, baA, mA, aq, K);
    #pragma unroll
    for (int h = 0; h < 2; h++) {
        int k = wq + h*8;
        float2 v = (nok && k < K) ? *(const float2*)(Wrow + k) : make_float2(0.f,0.f);
        wr[h*2] = v.x; wr[h*2+1] = v.y;
    }

    for (int it = 0; it < NIT; it++) {
        __syncthreads();
        #pragma unroll
        for (int h = 0; h < 2; h++)
            #pragma unroll
            for (int j = 0; j < 4; j++)
                As[aq + h*8 + j][arow] = ar[h*4 + j];
        #pragma unroll
        for (int h = 0; h < 2; h++)
            #pragma unroll
            for (int j = 0; j < 2; j++)
                Ws[wq + h*8 + j][wrow] = wr[h*2 + j];
        __syncthreads();
        if (it + 1 < NIT) {
            int k0 = (it + 1) * 16;
            ldA8<ASRC>(ar, A, lda, baA, mA, k0 + aq, K);
            #pragma unroll
            for (int h = 0; h < 2; h++) {
                int k = k0 + wq + h*8;
                float2 v = (nok && k < K) ? *(const float2*)(Wrow + k) : make_float2(0.f,0.f);
                wr[h*2] = v.x; wr[h*2+1] = v.y;
            }
        }
        #pragma unroll
        for (int kk = 0; kk < 16; kk++) {
            float4 a = *(const float4*)&As[kk][ty*4];
            float4 w = *(const float4*)&Ws[kk][tx*4];
            float am[4] = {a.x,a.y,a.z,a.w};
            float wn[4] = {w.x,w.y,w.z,w.w};
            #pragma unroll
            for (int i = 0; i < 4; i++)
                #pragma unroll
                for (int j = 0; j < 4; j++)
                    acc[i][j] = fmaf(am[i], wn[j], acc[i][j]);
        }
    }

    #pragma unroll
    for (int i = 0; i < 4; i++) {
        int m = m0 + ty*4 + i;
        #pragma unroll
        for (int j = 0; j < 4; j++) {
            int n = n0 + tx*4 + j;
            if (n < N) {
                float v = acc[i][j];
                if (biasC) v += biasC[n];
                if (Cadd) v += Cadd[(size_t)m*ldc + n];
                C[(size_t)m*ldc + n] = v;
            }
        }
    }
}

// ======= stage1: Q, PX, OX GEMMs + adj reduction ============================
#define QB 120
#define PXB 120
#define OXB 240
#define GEMMB (QB+PXB+OXB)      /* 480 */
#define ADJ_RPB 64
#define ADJ_BLOCKS (BBATCH*SSZ*SSZ/ADJ_RPB)   /* 9216 */

__global__ __launch_bounds__(128) void stage1(
    const float* __restrict__ adj, const float* __restrict__ X,
    const float* __restrict__ W0, const float* __restrict__ W1,
    const float* __restrict__ Wout, const float* __restrict__ bout)
{
    int bx = blockIdx.x;
    if (bx < QB) {               // Q = X @ W0^T
        ntB<0>(X, DD, DD, nullptr, W0, DD, HH, (bx/5)*64, (bx%5)*32,
               nullptr, nullptr, g_Q, HH);
        return;
    }
    if (bx < QB + PXB) {         // PX = X @ W1[:, :300]^T
        int t = bx - QB;
        ntB<0>(X, DD, DD, nullptr, W1, D1, HH, (t/5)*64, (t%5)*32,
               nullptr, nullptr, g_P, HH);
        return;
    }
    if (bx < GEMMB) {            // OX = X @ Wout^T + bout
        int t = bx - QB - PXB;
        ntB<0>(X, DD, DD, nullptr, Wout, DD, DD, (t/10)*64, (t%10)*32,
               bout, nullptr, g_OX, DD);
        return;
    }
    // ---- adj reduction: 64 rows/block, smem-staged ----
    __shared__ float buf[ADJ_RPB][51];
    __shared__ float swe[EE];
    int tid = threadIdx.x;
    if (tid < EE) swe[tid] = g_we[tid];
    size_t r0 = (size_t)(bx - GEMMB) * ADJ_RPB;
    const float4* src = (const float4*)(adj + r0 * EE);
    for (int idx = tid; idx < ADJ_RPB*EE/4; idx += 128) {
        float4 v = src[idx];
        int g = idx * 4;
        buf[(g  )/EE][(g  )%EE] = v.x;
        buf[(g+1)/EE][(g+1)%EE] = v.y;
        buf[(g+2)/EE][(g+2)%EE] = v.z;
        buf[(g+3)/EE][(g+3)%EE] = v.w;
    }
    __syncthreads();
    if (tid < ADJ_RPB) {
        float s0 = 0.f, s1 = 0.f;
        #pragma unroll 10
        for (int e = 0; e < EE; e++) {
            float v = buf[tid][e];
            s0 += v;
            s1 = fmaf(v, swe[e], s1);
        }
        g_A0[r0 + tid] = s0;
        g_A1[r0 + tid] = s1;
    }
}

// ======= bat body: batched NN GEMM, split-K x2, 64x32 tile, 128 thr =========
// MODE 0: partial of A0@Q ; MODE 1: partial of Atilde1@P (rank-2 fold in A)
template<int MODE>
__device__ __forceinline__ void bat_body(int gx, int gy, int zc) {
    __shared__ __align__(16) float As[16][68];
    __shared__ __align__(8)  float Bs[16][34];
    int b = zc >> 1, half = zc & 1;
    const float* A  = (MODE==0 ? g_A0 : g_A1) + (size_t)b * SSZ * SSZ;
    const float* Bm = (MODE==0 ? g_Q  : g_P ) + (size_t)b * SSZ * HH;
    float* Cp = (MODE==0) ? (half ? g_c0b : g_c0a) : (half ? g_c1b : g_c1a);
    int m0 = gy * 64, n0 = gx * 32;
    int tid = threadIdx.x;
    int arow = tid >> 1, aq = (tid & 1) * 4;
    int bk = tid >> 3, bn = (tid & 7) * 4;
    int tx = tid & 7, ty = tid >> 3;
    int kbase = half * 192;

    const float* Arow = A + (size_t)(m0 + arow) * SSZ + kbase;
    const float* s1p = g_s1 + b * SSZ + kbase;
    float s2i = 0.f;
    if (MODE == 1) s2i = g_s2[b*SSZ + m0 + arow] + g_sbh;

    float ar[8], br[4];
    float acc[4][4] = {};

    // prefetch it=0
    #pragma unroll
    for (int h = 0; h < 2; h++) {
        int k = aq + h*8;
        float4 v = *(const float4*)(Arow + k);
        if (MODE == 1) {
            float4 s = *(const float4*)(s1p + k);
            v.x += s.x + s2i; v.y += s.y + s2i; v.z += s.z + s2i; v.w += s.w + s2i;
        }
        ar[h*4]=v.x; ar[h*4+1]=v.y; ar[h*4+2]=v.z; ar[h*4+3]=v.w;
    }
    {
        const float* p = Bm + (size_t)(kbase + bk) * HH + n0 + bn;
        #pragma unroll
        for (int t = 0; t < 2; t++) {
            int n = n0 + bn + 2*t;
            float2 v = (n < HH) ? *(const float2*)(p + 2*t) : make_float2(0.f,0.f);
            br[2*t] = v.x; br[2*t+1] = v.y;
        }
    }

    for (int it = 0; it < 12; it++) {
        __syncthreads();
        #pragma unroll
        for (int h = 0; h < 2; h++)
            #pragma unroll
            for (int j = 0; j < 4; j++)
                As[aq + h*8 + j][arow] = ar[h*4 + j];
        #pragma unroll
        for (int j = 0; j < 4; j++) Bs[bk][bn + j] = br[j];
        __syncthreads();
        if (it + 1 < 12) {
            int k0 = (it + 1) * 16;
            #pragma unroll
            for (int h = 0; h < 2; h++) {
                int k = k0 + aq + h*8;
                float4 v = *(const float4*)(Arow + k);
                if (MODE == 1) {
                    float4 s = *(const float4*)(s1p + k);
                    v.x += s.x + s2i; v.y += s.y + s2i; v.z += s.z + s2i; v.w += s.w + s2i;
                }
                ar[h*4]=v.x; ar[h*4+1]=v.y; ar[h*4+2]=v.z; ar[h*4+3]=v.w;
            }
            const float* p = Bm + (size_t)(kbase + k0 + bk) * HH + n0 + bn;
            #pragma unroll
            for (int t = 0; t < 2; t++) {
                int n = n0 + bn + 2*t;
                float2 v = (n < HH) ? *(const float2*)(p + 2*t) : make_float2(0.f,0.f);
                br[2*t] = v.x; br[2*t+1] = v.y;
            }
        }
        #pragma unroll
        for (int kk = 0; kk < 16; kk++) {
            float4 a = *(const float4*)&As[kk][ty*4];
            float2 b0v = *(const float2*)&Bs[kk][tx*4];
            float2 b1v = *(const float2*)&Bs[kk][tx*4 + 2];
            float am[4] = {a.x,a.y,a.z,a.w};
            float wn[4] = {b0v.x,b0v.y,b1v.x,b1v.y};
            #pragma unroll
            for (int i = 0; i < 4; i++)
                #pragma unroll
                for (int j = 0; j < 4; j++)
                    acc[i][j] = fmaf(am[i], wn[j], acc[i][j]);
        }
    }

    #pragma unroll
    for (int i = 0; i < 4; i++) {
        int row = b*SSZ + m0 + ty*4 + i;
        #pragma unroll
        for (int j = 0; j < 4; j++) {
            int n = n0 + tx*4 + j;
            if (n < HH) Cp[(size_t)row*HH + n] = acc[i][j];
        }
    }
}

__global__ __launch_bounds__(128) void bat0() {
    bat_body<0>(blockIdx.x, blockIdx.y, blockIdx.z);
}

// ======= stage3: P += g0@W1b^T ; s1/s2  (OX moved to stage4) ================
#define PAB 120
__global__ __launch_bounds__(128) void stage3(const float* __restrict__ W1,
                                              const float* __restrict__ b0) {
    int bx = blockIdx.x;
    if (bx < PAB) {
        ntB<1>(nullptr, 0, HH, b0, W1 + DD, D1, HH, (bx/5)*64, (bx%5)*32,
               nullptr, g_P, g_P, HH);
        return;
    }
    // s1/s2: thread per row of g0 (recompute epilogue on load)
    __shared__ float sw1[HH], sw2[HH], sb0[HH];
    int tid = threadIdx.x;
    for (int i = tid; i < HH; i += 128) {
        sw1[i] = g_w1s[i]; sw2[i] = g_w2s[i]; sb0[i] = b0[i];
    }
    __syncthreads();
    int row = (bx - PAB) * 128 + tid;
    const float* pa = g_c0a + (size_t)row * HH;
    const float* pb = g_c0b + (size_t)row * HH;
    const float* pq = g_Q   + (size_t)row * HH;
    float a1 = 0.f, a2 = 0.f;
    for (int k = 0; k < HH; k += 2) {
        float2 a = *(const float2*)(pa + k);
        float2 b = *(const float2*)(pb + k);
        float2 q = *(const float2*)(pq + k);
        float gx = fmaxf(fmaf(a.x + b.x, INVE, q.x + 2.f*sb0[k]),   0.f);
        float gy = fmaxf(fmaf(a.y + b.y, INVE, q.y + 2.f*sb0[k+1]), 0.f);
        a1 = fmaf(gx, sw1[k], a1);  a1 = fmaf(gy, sw1[k+1], a1);
        a2 = fmaf(gx, sw2[k], a2);  a2 = fmaf(gy, sw2[k+1], a2);
    }
    g_s1[row] = a1;
    g_s2[row] = a2;
}

// ======= stage4: bat<1> merged with OX += g0@WoutA^T (independent work) =====
// grid (5, 6, 16): z<8 -> bat1 split-K blocks; z>=8 -> 240 OX tiles
__global__ __launch_bounds__(128) void stage4(const float* __restrict__ Wout,
                                              const float* __restrict__ b0) {
    if (blockIdx.z < 8) {
        bat_body<1>(blockIdx.x, blockIdx.y, blockIdx.z);
        return;
    }
    int t = (blockIdx.z - 8) * 30 + blockIdx.y * 5 + blockIdx.x;   // 0..239
    ntB<1>(nullptr, 0, HH, b0, Wout, DD, DD, (t/10)*64, (t%10)*32,
           nullptr, g_OX, g_OX, DD);
}

// ======= stage6: out = OX + g1@WoutB^T ======================================
#define OAB 240
__global__ __launch_bounds__(128) void stage6(const float* __restrict__ Wout,
                                              const float* __restrict__ b1,
                                              float* __restrict__ out) {
    int bx = blockIdx.x;
    ntB<2>(nullptr, 0, HH, b1, Wout + HH, DD, DD, (bx/10)*64, (bx%10)*32,
           nullptr, g_OX, out, DD);
}

// ======= launch =============================================================
extern "C" void kernel_launch(void* const* d_in, const int* in_sizes, int n_in,
                              void* d_out, int out_size) {
    const float* adj  = (const float*)d_in[0];
    const float* X    = (const float*)d_in[1];
    const float* W0   = (const float*)d_in[2];
    const float* b0   = (const float*)d_in[3];
    const float* W1   = (const float*)d_in[4];
    const float* b1   = (const float*)d_in[5];
    const float* Wh   = (const float*)d_in[6];
    const float* bh   = (const float*)d_in[7];
    const float* Wout = (const float*)d_in[8];
    const float* bout = (const float*)d_in[9];
    float* out = (float*)d_out;

    prep_weights<<<1, 256>>>(Wh, bh);

    // Q, PX, OX GEMMs overlapped with the 118MB adj streaming pass
    stage1<<<GEMMB + ADJ_BLOCKS, 128>>>(adj, X, W0, W1, Wout, bout);

    // split-K partials of A0@Q
    bat0<<<dim3(5, 6, 8), 128>>>();

    // P += g0@W1b^T ; s1/s2   (g0 epilogue fused in loads)
    stage3<<<PAB + 12, 128>>>(W1, b0);

    // bat1 split-K partials  MERGED with  OX += g0@WoutA^T (independent)
    stage4<<<dim3(5, 6, 16), 128>>>(Wout, b0);

    // out = OX + g1@WoutB^T   (g1 epilogue fused in loads)
    stage6<<<OAB, 128>>>(Wout, b1, out);
}